// round 12
// baseline (speedup 1.0000x reference)
#include <cuda_runtime.h>
#include <stdint.h>

#define NN 16384
#define DD 32
#define WPR (NN / 32)     // 512 u32 per dedup-bitmask row
#define LCAP 256          // per-node list capacity

// Canonical-pair dedup bitmask: bit for pair {a,b} (a<=b) lives at
// g_bits[a*WPR + (b>>5)]. Row r only ever holds bits in words >= r>>5;
// agg does a triangular clear of exactly that span each launch.
__device__ uint32_t g_bits[(size_t)NN * WPR];
__device__ int g_list[(size_t)NN * LCAP];
__device__ int g_cnt[NN];

// 2 edges per thread, 1024 blocks: 4x resident threads vs 8-edge version ->
// 4x outstanding atomics chip-wide. ONE canonical atomicOr per edge.
__global__ void __launch_bounds__(256) build_kernel(const int* __restrict__ src,
                                                    const int* __restrict__ dst,
                                                    int E2) {
    int t = blockIdx.x * blockDim.x + threadIdx.x;
    if (t >= E2) return;
    int2 s2 = __ldg(reinterpret_cast<const int2*>(src) + t);
    int2 d2 = __ldg(reinterpret_cast<const int2*>(dst) + t);

    int s[2] = {s2.x, s2.y};
    int d[2] = {d2.x, d2.y};

    int a[2], b[2];
#pragma unroll
    for (int i = 0; i < 2; i++) {
        a[i] = s[i] < d[i] ? s[i] : d[i];
        b[i] = s[i] < d[i] ? d[i] : s[i];
    }

    unsigned old[2];
#pragma unroll
    for (int i = 0; i < 2; i++)
        old[i] = atomicOr(&g_bits[(size_t)a[i] * WPR + (b[i] >> 5)], 1u << (b[i] & 31));

#pragma unroll
    for (int i = 0; i < 2; i++) {
        if (!(old[i] & (1u << (b[i] & 31)))) {    // first time pair {a,b} seen
            int p = atomicAdd(&g_cnt[a[i]], 1);
            if (p < LCAP) g_list[(size_t)a[i] * LCAP + p] = b[i];
            if (a[i] != b[i]) {
                p = atomicAdd(&g_cnt[b[i]], 1);
                if (p < LCAP) g_list[(size_t)b[i] * LCAP + p] = a[i];
            }
        }
    }
}

// One warp per node. Front-batched unguarded index preload, branchless
// 16-LDG gather for slots 0..63, guarded 64..95, rare tail, TRIANGULAR
// bitmask clear, fused 32x32 epilogue. Barrier sits BEFORE the gather.
__global__ void __launch_bounds__(256, 6) agg_kernel(const float* __restrict__ x,
                                                     const float* __restrict__ W_agg,
                                                     const float* __restrict__ b_agg,
                                                     const float* __restrict__ W_upd,
                                                     const float* __restrict__ b_upd,
                                                     float* __restrict__ out) {
    __shared__ float WaggT[DD * DD];   // [d][c] = W_agg[c][d]
    __shared__ float WupdT[DD * DD];
    __shared__ float bsum[DD];
    __shared__ float msgsm[8][DD];
    __shared__ float xsm[8][DD];

    int tid  = threadIdx.x;
    int warp = tid >> 5;
    int lane = tid & 31;
    int row  = blockIdx.x * 8 + warp;

    const int* lst = g_list + (size_t)row * LCAP;

    // Front-batched independent loads: 3 index words + own x row + cnt.
    int i0 = __ldg(lst + lane);
    int i1 = __ldg(lst + 32 + lane);
    int i2 = __ldg(lst + 64 + lane);
    float xown = x[(size_t)row * DD + lane];
    int cnt = g_cnt[row];
    cnt = cnt < LCAP ? cnt : LCAP;
    if (lane == 0) g_cnt[row] = 0;        // reset for next replay

    for (int i = tid; i < DD * DD; i += blockDim.x) {
        int c = i >> 5, d = i & 31;
        WaggT[d * DD + c] = W_agg[i];
        WupdT[d * DD + c] = W_upd[i];
    }
    if (tid < DD) bsum[tid] = b_agg[tid] + b_upd[tid];
    __syncthreads();   // weight smem ready; no barrier after the gather

    int g = lane >> 3;        // gather group 0..3
    int q = lane & 7;         // float4 slot within a 128B row

    const float4* x4 = reinterpret_cast<const float4*>(x);
    float4 A0 = make_float4(0.f, 0.f, 0.f, 0.f);
    float4 A1 = A0;

    // ---- Block 1: slots 0..63, fully branchless (16 independent LDG.128).
#pragma unroll
    for (int u = 0; u < 8; u++) {
        int slot = (u << 2) + g;
        int j = __shfl_sync(0xffffffffu, i0, slot);
        float w = (slot < cnt) ? 1.0f : 0.0f;
        float4 v = x4[(size_t)j * 8 + q];
        float4& A = (u & 1) ? A1 : A0;
        A.x = fmaf(w, v.x, A.x); A.y = fmaf(w, v.y, A.y);
        A.z = fmaf(w, v.z, A.z); A.w = fmaf(w, v.w, A.w);
    }
#pragma unroll
    for (int u = 0; u < 8; u++) {
        int slot = (u << 2) + g;
        int j = __shfl_sync(0xffffffffu, i1, slot);
        float w = (32 + slot < cnt) ? 1.0f : 0.0f;
        float4 v = x4[(size_t)j * 8 + q];
        float4& A = (u & 1) ? A1 : A0;
        A.x = fmaf(w, v.x, A.x); A.y = fmaf(w, v.y, A.y);
        A.z = fmaf(w, v.z, A.z); A.w = fmaf(w, v.w, A.w);
    }

    // ---- Block 2: slots 64..95 (about half of rows enter).
    if (cnt > 64) {
        int ng = cnt - 64;  ng = ng > 32 ? 32 : ng;
        int nu = (ng + 3) >> 2;
#pragma unroll
        for (int u = 0; u < 8; u++) {
            if (u < nu) {
                int slot = (u << 2) + g;
                int j = __shfl_sync(0xffffffffu, i2, slot);
                float w = (slot < ng) ? 1.0f : 0.0f;
                float4 v = x4[(size_t)j * 8 + q];
                float4& A = (u & 1) ? A1 : A0;
                A.x = fmaf(w, v.x, A.x); A.y = fmaf(w, v.y, A.y);
                A.z = fmaf(w, v.z, A.z); A.w = fmaf(w, v.w, A.w);
            }
        }
    }

    // ---- Rare tail: slots 96..255 (Poisson(64): ~never; kept for correctness).
    for (int k = 3; k < 8; k++) {
        int base = k << 5;
        if (base >= cnt) break;
        int ik = __ldg(lst + base + lane);
        int ng = cnt - base;  ng = ng > 32 ? 32 : ng;
        int nu = (ng + 3) >> 2;
        for (int u = 0; u < 8; u++) {
            if (u < nu) {
                int slot = (u << 2) + g;
                int j = __shfl_sync(0xffffffffu, ik, slot);
                float w = (slot < ng) ? 1.0f : 0.0f;
                float4 v = x4[(size_t)j * 8 + q];
                A0.x = fmaf(w, v.x, A0.x); A0.y = fmaf(w, v.y, A0.y);
                A0.z = fmaf(w, v.z, A0.z); A0.w = fmaf(w, v.w, A0.w);
            }
        }
    }

    // ---- Triangular clear: canonical row r holds bits only in words >= r>>5.
    // Clear uint4-aligned span [ (r>>5) & ~3, 512 ): avg 1KB, coalesced.
    {
        uint4* rv = reinterpret_cast<uint4*>(g_bits + (size_t)row * WPR);
        const uint4 z = make_uint4(0u, 0u, 0u, 0u);
        int s4 = (row >> 7);           // ((row>>5) & ~3) / 4 == row >> 7
        for (int v = s4 + lane; v < WPR / 4; v += 32)
            rv[v] = z;
    }

    // Reduce 2 accumulators, then across the 4 lane-groups (xor 8, xor 16).
    float4 s;
    s.x = A0.x + A1.x;  s.y = A0.y + A1.y;
    s.z = A0.z + A1.z;  s.w = A0.w + A1.w;
#pragma unroll
    for (int off = 8; off <= 16; off <<= 1) {
        s.x += __shfl_xor_sync(0xffffffffu, s.x, off);
        s.y += __shfl_xor_sync(0xffffffffu, s.y, off);
        s.z += __shfl_xor_sync(0xffffffffu, s.z, off);
        s.w += __shfl_xor_sync(0xffffffffu, s.w, off);
    }
    if (lane < 8)
        *reinterpret_cast<float4*>(&msgsm[warp][q << 2]) = s;
    xsm[warp][lane] = xown;
    __syncwarp();

    // Fused epilogue: out[row][c] = sum_d msg[d]*W_agg[c][d] + x[row][d]*W_upd[c][d] + b
    float o = bsum[lane];
#pragma unroll
    for (int d = 0; d < DD; d++) {
        o = fmaf(msgsm[warp][d], WaggT[d * DD + lane],
            fmaf(xsm[warp][d],  WupdT[d * DD + lane], o));
    }
    out[(size_t)row * DD + lane] = o;
}

extern "C" void kernel_launch(void* const* d_in, const int* in_sizes, int n_in,
                              void* d_out, int out_size) {
    const float* x     = (const float*)d_in[0];
    const int*   ei    = (const int*)d_in[1];     // [2, E]: row0=src, row1=dst
    const float* W_agg = (const float*)d_in[2];
    const float* b_agg = (const float*)d_in[3];
    const float* W_upd = (const float*)d_in[4];
    const float* b_upd = (const float*)d_in[5];
    float* out = (float*)d_out;

    int E  = in_sizes[1] / 2;
    int E2 = E / 2;                               // E = 524288, divisible by 2

    build_kernel<<<(E2 + 255) / 256, 256>>>(ei, ei + E, E2);
    agg_kernel<<<NN / 8, 256>>>(x, W_agg, b_agg, W_upd, b_upd, out);
}

// round 13
// speedup vs baseline: 1.2044x; 1.2044x over previous
#include <cuda_runtime.h>
#include <stdint.h>

#define NN 16384
#define DD 32
#define WPR (NN / 32)     // 512 u32 per dedup-bitmask row
#define LCAP 256          // per-node list capacity

// Canonical-pair dedup bitmask: bit for pair {a,b} (a<=b) lives at
// g_bits[a*WPR + (b>>5)]. agg blanket-clears each row stripe per launch.
__device__ uint32_t g_bits[(size_t)NN * WPR];
__device__ int g_list[(size_t)NN * LCAP];
__device__ int g_cnt[NN];

// 2 edges per thread, 1024 blocks. ONE canonical atomicOr per edge.
__global__ void __launch_bounds__(256) build_kernel(const int* __restrict__ src,
                                                    const int* __restrict__ dst,
                                                    int E2) {
    int t = blockIdx.x * blockDim.x + threadIdx.x;
    if (t >= E2) return;
    int2 s2 = __ldg(reinterpret_cast<const int2*>(src) + t);
    int2 d2 = __ldg(reinterpret_cast<const int2*>(dst) + t);

    int s[2] = {s2.x, s2.y};
    int d[2] = {d2.x, d2.y};

    int a[2], b[2];
#pragma unroll
    for (int i = 0; i < 2; i++) {
        a[i] = s[i] < d[i] ? s[i] : d[i];
        b[i] = s[i] < d[i] ? d[i] : s[i];
    }

    unsigned old[2];
#pragma unroll
    for (int i = 0; i < 2; i++)
        old[i] = atomicOr(&g_bits[(size_t)a[i] * WPR + (b[i] >> 5)], 1u << (b[i] & 31));

#pragma unroll
    for (int i = 0; i < 2; i++) {
        if (!(old[i] & (1u << (b[i] & 31)))) {    // first time pair {a,b} seen
            int p = atomicAdd(&g_cnt[a[i]], 1);
            if (p < LCAP) g_list[(size_t)a[i] * LCAP + p] = b[i];
            if (a[i] != b[i]) {
                p = atomicAdd(&g_cnt[b[i]], 1);
                if (p < LCAP) g_list[(size_t)b[i] * LCAP + p] = a[i];
            }
        }
    }
}

// TWO rows per warp: doubled per-warp MLP so one latency exposure covers two
// rows' worth of loads. 32-LDG straight-line gather block for slots 0..63 of
// both rows; guarded 64..95; rare tails; blanket clears; dual fused epilogue.
__global__ void __launch_bounds__(256, 5) agg_kernel(const float* __restrict__ x,
                                                     const float* __restrict__ W_agg,
                                                     const float* __restrict__ b_agg,
                                                     const float* __restrict__ W_upd,
                                                     const float* __restrict__ b_upd,
                                                     float* __restrict__ out) {
    __shared__ float WaggT[DD * DD];   // [d][c] = W_agg[c][d]
    __shared__ float WupdT[DD * DD];
    __shared__ float bsum[DD];
    __shared__ float msgsm[16][DD];
    __shared__ float xsm[16][DD];

    int tid  = threadIdx.x;
    int warp = tid >> 5;
    int lane = tid & 31;
    int r0   = blockIdx.x * 16 + warp * 2;   // rows r0, r0+1
    int r1   = r0 + 1;

    const int* la = g_list + (size_t)r0 * LCAP;
    const int* lb = g_list + (size_t)r1 * LCAP;

    // Front-batched independent loads for BOTH rows.
    int i0a = __ldg(la + lane);
    int i1a = __ldg(la + 32 + lane);
    int i2a = __ldg(la + 64 + lane);
    int i0b = __ldg(lb + lane);
    int i1b = __ldg(lb + 32 + lane);
    int i2b = __ldg(lb + 64 + lane);
    float xa = x[(size_t)r0 * DD + lane];
    float xb = x[(size_t)r1 * DD + lane];
    int ca = g_cnt[r0];  ca = ca < LCAP ? ca : LCAP;
    int cb = g_cnt[r1];  cb = cb < LCAP ? cb : LCAP;
    if (lane == 0) g_cnt[r0] = 0;
    if (lane == 1) g_cnt[r1] = 0;

    for (int i = tid; i < DD * DD; i += blockDim.x) {
        int c = i >> 5, d = i & 31;
        WaggT[d * DD + c] = W_agg[i];
        WupdT[d * DD + c] = W_upd[i];
    }
    if (tid < DD) bsum[tid] = b_agg[tid] + b_upd[tid];
    __syncthreads();

    int g = lane >> 3;        // gather group 0..3
    int q = lane & 7;         // float4 slot within a 128B row

    const float4* x4 = reinterpret_cast<const float4*>(x);
    float4 Aa = make_float4(0.f, 0.f, 0.f, 0.f);
    float4 Ab = Aa;

    // ---- Slots 0..63 of BOTH rows: 32 independent LDG.128, straight-line.
#pragma unroll
    for (int u = 0; u < 8; u++) {
        int slot = (u << 2) + g;
        int ja = __shfl_sync(0xffffffffu, i0a, slot);
        int jb = __shfl_sync(0xffffffffu, i0b, slot);
        float wa = (slot < ca) ? 1.0f : 0.0f;
        float wb = (slot < cb) ? 1.0f : 0.0f;
        float4 va = x4[(size_t)ja * 8 + q];
        float4 vb = x4[(size_t)jb * 8 + q];
        Aa.x = fmaf(wa, va.x, Aa.x); Aa.y = fmaf(wa, va.y, Aa.y);
        Aa.z = fmaf(wa, va.z, Aa.z); Aa.w = fmaf(wa, va.w, Aa.w);
        Ab.x = fmaf(wb, vb.x, Ab.x); Ab.y = fmaf(wb, vb.y, Ab.y);
        Ab.z = fmaf(wb, vb.z, Ab.z); Ab.w = fmaf(wb, vb.w, Ab.w);
    }
#pragma unroll
    for (int u = 0; u < 8; u++) {
        int slot = (u << 2) + g;
        int ja = __shfl_sync(0xffffffffu, i1a, slot);
        int jb = __shfl_sync(0xffffffffu, i1b, slot);
        float wa = (32 + slot < ca) ? 1.0f : 0.0f;
        float wb = (32 + slot < cb) ? 1.0f : 0.0f;
        float4 va = x4[(size_t)ja * 8 + q];
        float4 vb = x4[(size_t)jb * 8 + q];
        Aa.x = fmaf(wa, va.x, Aa.x); Aa.y = fmaf(wa, va.y, Aa.y);
        Aa.z = fmaf(wa, va.z, Aa.z); Aa.w = fmaf(wa, va.w, Aa.w);
        Ab.x = fmaf(wb, vb.x, Ab.x); Ab.y = fmaf(wb, vb.y, Ab.y);
        Ab.z = fmaf(wb, vb.z, Ab.z); Ab.w = fmaf(wb, vb.w, Ab.w);
    }

    // ---- Slots 64..95 (about half the rows enter each branch).
    if (ca > 64) {
        int ng = ca - 64;  ng = ng > 32 ? 32 : ng;
        int nu = (ng + 3) >> 2;
#pragma unroll
        for (int u = 0; u < 8; u++) {
            if (u < nu) {
                int slot = (u << 2) + g;
                int j = __shfl_sync(0xffffffffu, i2a, slot);
                float w = (slot < ng) ? 1.0f : 0.0f;
                float4 v = x4[(size_t)j * 8 + q];
                Aa.x = fmaf(w, v.x, Aa.x); Aa.y = fmaf(w, v.y, Aa.y);
                Aa.z = fmaf(w, v.z, Aa.z); Aa.w = fmaf(w, v.w, Aa.w);
            }
        }
    }
    if (cb > 64) {
        int ng = cb - 64;  ng = ng > 32 ? 32 : ng;
        int nu = (ng + 3) >> 2;
#pragma unroll
        for (int u = 0; u < 8; u++) {
            if (u < nu) {
                int slot = (u << 2) + g;
                int j = __shfl_sync(0xffffffffu, i2b, slot);
                float w = (slot < ng) ? 1.0f : 0.0f;
                float4 v = x4[(size_t)j * 8 + q];
                Ab.x = fmaf(w, v.x, Ab.x); Ab.y = fmaf(w, v.y, Ab.y);
                Ab.z = fmaf(w, v.z, Ab.z); Ab.w = fmaf(w, v.w, Ab.w);
            }
        }
    }

    // ---- Rare tails: slots 96..255 (Poisson(64): ~never; correctness only).
    for (int k = 3; k < 8; k++) {
        int base = k << 5;
        if (base >= ca) break;
        int ik = __ldg(la + base + lane);
        int ng = ca - base;  ng = ng > 32 ? 32 : ng;
        int nu = (ng + 3) >> 2;
        for (int u = 0; u < 8; u++) {
            if (u < nu) {
                int slot = (u << 2) + g;
                int j = __shfl_sync(0xffffffffu, ik, slot);
                float w = (slot < ng) ? 1.0f : 0.0f;
                float4 v = x4[(size_t)j * 8 + q];
                Aa.x = fmaf(w, v.x, Aa.x); Aa.y = fmaf(w, v.y, Aa.y);
                Aa.z = fmaf(w, v.z, Aa.z); Aa.w = fmaf(w, v.w, Aa.w);
            }
        }
    }
    for (int k = 3; k < 8; k++) {
        int base = k << 5;
        if (base >= cb) break;
        int ik = __ldg(lb + base + lane);
        int ng = cb - base;  ng = ng > 32 ? 32 : ng;
        int nu = (ng + 3) >> 2;
        for (int u = 0; u < 8; u++) {
            if (u < nu) {
                int slot = (u << 2) + g;
                int j = __shfl_sync(0xffffffffu, ik, slot);
                float w = (slot < ng) ? 1.0f : 0.0f;
                float4 v = x4[(size_t)j * 8 + q];
                Ab.x = fmaf(w, v.x, Ab.x); Ab.y = fmaf(w, v.y, Ab.y);
                Ab.z = fmaf(w, v.z, Ab.z); Ab.w = fmaf(w, v.w, Ab.w);
            }
        }
    }

    // Blanket clear of both rows' 2KB bitmask stripes (coalesced STG.128).
    {
        uint4* ra = reinterpret_cast<uint4*>(g_bits + (size_t)r0 * WPR);
        uint4* rb = reinterpret_cast<uint4*>(g_bits + (size_t)r1 * WPR);
        const uint4 z = make_uint4(0u, 0u, 0u, 0u);
        ra[lane] = z; ra[lane + 32] = z; ra[lane + 64] = z; ra[lane + 96] = z;
        rb[lane] = z; rb[lane + 32] = z; rb[lane + 64] = z; rb[lane + 96] = z;
    }

    // Cross-group reduce for both rows (xor 8, xor 16).
#pragma unroll
    for (int off = 8; off <= 16; off <<= 1) {
        Aa.x += __shfl_xor_sync(0xffffffffu, Aa.x, off);
        Aa.y += __shfl_xor_sync(0xffffffffu, Aa.y, off);
        Aa.z += __shfl_xor_sync(0xffffffffu, Aa.z, off);
        Aa.w += __shfl_xor_sync(0xffffffffu, Aa.w, off);
        Ab.x += __shfl_xor_sync(0xffffffffu, Ab.x, off);
        Ab.y += __shfl_xor_sync(0xffffffffu, Ab.y, off);
        Ab.z += __shfl_xor_sync(0xffffffffu, Ab.z, off);
        Ab.w += __shfl_xor_sync(0xffffffffu, Ab.w, off);
    }
    int w2 = warp * 2;
    if (lane < 8) {
        *reinterpret_cast<float4*>(&msgsm[w2][q << 2])     = Aa;
        *reinterpret_cast<float4*>(&msgsm[w2 + 1][q << 2]) = Ab;
    }
    xsm[w2][lane]     = xa;
    xsm[w2 + 1][lane] = xb;
    __syncwarp();

    // Dual fused epilogue.
    float oa = bsum[lane];
    float ob = oa;
#pragma unroll
    for (int d = 0; d < DD; d++) {
        float wag = WaggT[d * DD + lane];
        float wup = WupdT[d * DD + lane];
        oa = fmaf(msgsm[w2][d],     wag, fmaf(xsm[w2][d],     wup, oa));
        ob = fmaf(msgsm[w2 + 1][d], wag, fmaf(xsm[w2 + 1][d], wup, ob));
    }
    out[(size_t)r0 * DD + lane] = oa;
    out[(size_t)r1 * DD + lane] = ob;
}

extern "C" void kernel_launch(void* const* d_in, const int* in_sizes, int n_in,
                              void* d_out, int out_size) {
    const float* x     = (const float*)d_in[0];
    const int*   ei    = (const int*)d_in[1];     // [2, E]: row0=src, row1=dst
    const float* W_agg = (const float*)d_in[2];
    const float* b_agg = (const float*)d_in[3];
    const float* W_upd = (const float*)d_in[4];
    const float* b_upd = (const float*)d_in[5];
    float* out = (float*)d_out;

    int E  = in_sizes[1] / 2;
    int E2 = E / 2;                               // E = 524288, divisible by 2

    build_kernel<<<(E2 + 255) / 256, 256>>>(ei, ei + E, E2);
    agg_kernel<<<NN / 16, 256>>>(x, W_agg, b_agg, W_upd, b_upd, out);
}